// round 13
// baseline (speedup 1.0000x reference)
#include <cuda_runtime.h>
#include <cuda_bf16.h>
#include <cuda_fp16.h>

#define N_NODES 50000
#define N_EDGES 800000
#define D 128

// ---------------- device scratch (no runtime allocation allowed) ----------
__device__ int   g_deg[N_NODES];
__device__ int   g_rowptr[N_NODES + 1];
__device__ int   g_fill[N_NODES];
__device__ int   g_col[N_EDGES];
__device__ int   g_not64;
__device__ int   g_blk_agg[64];
__device__ int   g_blk_incl[64];
__device__ int   g_blk_flag[64];

__device__ __nv_bfloat16 g_aggb[N_NODES * D];
__device__ __nv_bfloat16 g_aggs[N_NODES * D];
__device__ __nv_bfloat16 g_xb[N_NODES * D];
__device__ __nv_bfloat16 g_xs[N_NODES * D];
__device__ __half        g_xh[N_NODES * D];    // fp16 mirror for gather
__device__ __nv_bfloat16 g_h1b[N_NODES * D];
__device__ __nv_bfloat16 g_h1s[N_NODES * D];
__device__ __half        g_h1h[N_NODES * D];   // fp16 mirror of h1
__device__ __nv_bfloat16 g_Wb[4 * 128 * 128];  // Wt hi: [mat][n][k]
__device__ __nv_bfloat16 g_Ws[4 * 128 * 128];  // Wt lo

// ---------------- helpers ---------------------------------------------------
__device__ __forceinline__ unsigned int pkbf(float a, float b) {
    __nv_bfloat16 ha = __float2bfloat16(a), hb = __float2bfloat16(b);
    return ((unsigned int)__bfloat16_as_ushort(hb) << 16) |
           (unsigned int)__bfloat16_as_ushort(ha);
}

__device__ __forceinline__ void cp_async16(unsigned int dst, const void* src) {
    asm volatile("cp.async.ca.shared.global [%0], [%1], 16;"
                 :: "r"(dst), "l"(src) : "memory");
}
__device__ __forceinline__ void cp_async16z(unsigned int dst, const void* src, int sz) {
    asm volatile("cp.async.ca.shared.global [%0], [%1], 16, %2;"
                 :: "r"(dst), "l"(src), "r"(sz) : "memory");
}
__device__ __forceinline__ void cp_commit() {
    asm volatile("cp.async.commit_group;" ::: "memory");
}
__device__ __forceinline__ void cp_wait0() {
    asm volatile("cp.async.wait_group 0;" ::: "memory");
}
__device__ __forceinline__ void cp_wait1() {
    asm volatile("cp.async.wait_group 1;" ::: "memory");
}

// bf16 m16n8k16 row.col mma, fp32 accumulate
__device__ __forceinline__ void mma16816(float* d, const unsigned int* a,
                                         const unsigned int* b) {
    asm volatile(
        "mma.sync.aligned.m16n8k16.row.col.f32.bf16.bf16.f32 "
        "{%0,%1,%2,%3}, {%4,%5,%6,%7}, {%8,%9}, {%0,%1,%2,%3};"
        : "+f"(d[0]), "+f"(d[1]), "+f"(d[2]), "+f"(d[3])
        : "r"(a[0]), "r"(a[1]), "r"(a[2]), "r"(a[3]), "r"(b[0]), "r"(b[1]));
}

// ---------------- prep: zero + dtype probe + weight & x conversion ---------
__global__ void prep_kernel(const int* __restrict__ ei32,
                            const float4* __restrict__ x,
                            const float* __restrict__ W1l,
                            const float* __restrict__ W1r,
                            const float* __restrict__ W2l,
                            const float* __restrict__ W2r,
                            int n) {
    int i = blockIdx.x * blockDim.x + threadIdx.x;
    if (i < n) g_deg[i] = 0;
    if (i < 64) g_blk_flag[i] = 0;
    if (blockIdx.x == 0) {
        if (threadIdx.x == 0) g_not64 = 0;
        __syncthreads();
        if (threadIdx.x < 256 && ei32[2 * threadIdx.x + 1] != 0)
            atomicOr(&g_not64, 1);
    }
    if (i < 4 * 16384) {
        int m = i >> 14;
        int t = i & 16383;
        int nn = t >> 7, kk = t & 127;
        const float* W = (m == 0) ? W1l : (m == 1) ? W1r : (m == 2) ? W2l : W2r;
        float f = W[kk * 128 + nn];
        __nv_bfloat16 hb = __float2bfloat16(f);
        g_Wb[m * 16384 + nn * 128 + kk] = hb;
        g_Ws[m * 16384 + nn * 128 + kk] =
            __float2bfloat16(f - __bfloat162float(hb));
    }
    if (i < n * 32) {
        float4 v = x[i];
        __nv_bfloat16 b0 = __float2bfloat16(v.x), b1 = __float2bfloat16(v.y);
        __nv_bfloat16 b2 = __float2bfloat16(v.z), b3 = __float2bfloat16(v.w);
        uint2 whi, wlo;
        whi.x = ((unsigned)__bfloat16_as_ushort(b1) << 16) | __bfloat16_as_ushort(b0);
        whi.y = ((unsigned)__bfloat16_as_ushort(b3) << 16) | __bfloat16_as_ushort(b2);
        wlo.x = pkbf(v.x - __bfloat162float(b0), v.y - __bfloat162float(b1));
        wlo.y = pkbf(v.z - __bfloat162float(b2), v.w - __bfloat162float(b3));
        ((uint2*)g_xb)[i] = whi;
        ((uint2*)g_xs)[i] = wlo;
        __half2 h01 = __floats2half2_rn(v.x, v.y);
        __half2 h23 = __floats2half2_rn(v.z, v.w);
        ((uint2*)g_xh)[i] = make_uint2(*(unsigned int*)&h01, *(unsigned int*)&h23);
    }
}

__global__ void hist_kernel(const void* __restrict__ eiv, int E) {
    int e = blockIdx.x * blockDim.x + threadIdx.x;
    if (e >= E) return;
    int d;
    if (g_not64) d = ((const int*)eiv)[E + e];
    else         d = (int)((const long long*)eiv)[E + e];
    atomicAdd(&g_deg[d], 1);
}

__global__ void scan_lookback_kernel(int n, int nb) {
    const int b = blockIdx.x;
    const int t = threadIdx.x;
    const int lane = t & 31, wid = t >> 5;
    int i0 = b * 1024 + t * 4;

    int vals[4]; int local = 0;
#pragma unroll
    for (int u = 0; u < 4; u++) {
        int i = i0 + u;
        vals[u] = (i < n) ? g_deg[i] : 0;
        local += vals[u];
    }
    int incl = local;
#pragma unroll
    for (int off = 1; off < 32; off <<= 1) {
        int u = __shfl_up_sync(0xffffffffu, incl, off);
        if (lane >= off) incl += u;
    }
    __shared__ int ws[8], wexcl[8];
    __shared__ int s_prefix;
    if (lane == 31) ws[wid] = incl;
    __syncthreads();
    if (t < 8) {
        int s = ws[t];
        int si = s;
#pragma unroll
        for (int off = 1; off < 8; off <<= 1) {
            int u = __shfl_up_sync(0xffu, si, off);
            if (t >= off) si += u;
        }
        wexcl[t] = si - s;
    }
    __syncthreads();
    const int total = wexcl[7] + ws[7];

    if (t == 0) {
        g_blk_agg[b] = total;
        __threadfence();
        ((volatile int*)g_blk_flag)[b] = 1;
    }
    if (wid == 0) {
        int prefix = 0;
        int j = b - 1;
        while (j >= 0) {
            int jj = j - lane;
            int f = 0, v = 0;
            if (jj >= 0) {
                do { f = ((volatile int*)g_blk_flag)[jj]; } while (f == 0);
                __threadfence();
                v = (f == 2) ? ((volatile int*)g_blk_incl)[jj]
                             : ((volatile int*)g_blk_agg)[jj];
            }
            unsigned done = __ballot_sync(0xffffffffu, jj >= 0 && f == 2);
            if (done) {
                int fl = __ffs(done) - 1;
                int contrib = (lane <= fl) ? v : 0;
#pragma unroll
                for (int off = 16; off; off >>= 1)
                    contrib += __shfl_xor_sync(0xffffffffu, contrib, off);
                prefix += contrib;
                break;
            } else {
                int contrib = (jj >= 0) ? v : 0;
#pragma unroll
                for (int off = 16; off; off >>= 1)
                    contrib += __shfl_xor_sync(0xffffffffu, contrib, off);
                prefix += contrib;
                j -= 32;
            }
        }
        if (lane == 0) {
            g_blk_incl[b] = prefix + total;
            __threadfence();
            ((volatile int*)g_blk_flag)[b] = 2;
            s_prefix = prefix;
            if (b == nb - 1) g_rowptr[n] = prefix + total;
        }
    }
    __syncthreads();

    int excl = s_prefix + wexcl[wid] + (incl - local);
#pragma unroll
    for (int u = 0; u < 4; u++) {
        int i = i0 + u;
        if (i < n) { g_rowptr[i] = excl; g_fill[i] = excl; }
        excl += vals[u];
    }
}

__global__ void scatter_kernel(const void* __restrict__ eiv, int E) {
    int e = blockIdx.x * blockDim.x + threadIdx.x;
    if (e >= E) return;
    int s, d;
    if (g_not64) {
        s = ((const int*)eiv)[e];
        d = ((const int*)eiv)[E + e];
    } else {
        s = (int)((const long long*)eiv)[e];
        d = (int)((const long long*)eiv)[E + e];
    }
    int pos = atomicAdd(&g_fill[d], 1);
    g_col[pos] = s;
}

// ---------------- mean aggregation: warp/node, unroll 8 --------------------
__global__ void aggregate_kernel(int n, int use_h1) {
    int warp = (blockIdx.x * blockDim.x + threadIdx.x) >> 5;
    int lane = threadIdx.x & 31;
    if (warp >= n) return;
    const uint2* __restrict__ src =
        use_h1 ? (const uint2*)g_h1h : (const uint2*)g_xh;
    int beg = g_rowptr[warp];
    int end = g_rowptr[warp + 1];
    float4 acc = make_float4(0.f, 0.f, 0.f, 0.f);
    int e = beg;
    for (; e + 8 <= end; e += 8) {
        int s0 = g_col[e],     s1 = g_col[e + 1], s2 = g_col[e + 2], s3 = g_col[e + 3];
        int s4 = g_col[e + 4], s5 = g_col[e + 5], s6 = g_col[e + 6], s7 = g_col[e + 7];
        uint2 v0 = src[(long)s0 * 32 + lane];
        uint2 v1 = src[(long)s1 * 32 + lane];
        uint2 v2 = src[(long)s2 * 32 + lane];
        uint2 v3 = src[(long)s3 * 32 + lane];
        uint2 v4 = src[(long)s4 * 32 + lane];
        uint2 v5 = src[(long)s5 * 32 + lane];
        uint2 v6 = src[(long)s6 * 32 + lane];
        uint2 v7 = src[(long)s7 * 32 + lane];
#pragma unroll
        for (int q = 0; q < 8; q++) {
            uint2 v = (q == 0) ? v0 : (q == 1) ? v1 : (q == 2) ? v2 : (q == 3) ? v3
                    : (q == 4) ? v4 : (q == 5) ? v5 : (q == 6) ? v6 : v7;
            float2 f0 = __half22float2(*(__half2*)&v.x);
            float2 f1 = __half22float2(*(__half2*)&v.y);
            acc.x += f0.x; acc.y += f0.y; acc.z += f1.x; acc.w += f1.y;
        }
    }
    for (; e + 4 <= end; e += 4) {
        int s0 = g_col[e], s1 = g_col[e + 1], s2 = g_col[e + 2], s3 = g_col[e + 3];
        uint2 v0 = src[(long)s0 * 32 + lane];
        uint2 v1 = src[(long)s1 * 32 + lane];
        uint2 v2 = src[(long)s2 * 32 + lane];
        uint2 v3 = src[(long)s3 * 32 + lane];
#pragma unroll
        for (int q = 0; q < 4; q++) {
            uint2 v = (q == 0) ? v0 : (q == 1) ? v1 : (q == 2) ? v2 : v3;
            float2 f0 = __half22float2(*(__half2*)&v.x);
            float2 f1 = __half22float2(*(__half2*)&v.y);
            acc.x += f0.x; acc.y += f0.y; acc.z += f1.x; acc.w += f1.y;
        }
    }
    for (; e < end; ++e) {
        int s = g_col[e];
        uint2 v = src[(long)s * 32 + lane];
        float2 f0 = __half22float2(*(__half2*)&v.x);
        float2 f1 = __half22float2(*(__half2*)&v.y);
        acc.x += f0.x; acc.y += f0.y; acc.z += f1.x; acc.w += f1.y;
    }
    int deg = end - beg;
    float sc = 1.0f / (float)(deg > 0 ? deg : 1);
    acc.x *= sc; acc.y *= sc; acc.z *= sc; acc.w *= sc;

    __nv_bfloat16 b0 = __float2bfloat16(acc.x), b1 = __float2bfloat16(acc.y);
    __nv_bfloat16 b2 = __float2bfloat16(acc.z), b3 = __float2bfloat16(acc.w);
    uint2 whi, wlo;
    whi.x = ((unsigned)__bfloat16_as_ushort(b1) << 16) | __bfloat16_as_ushort(b0);
    whi.y = ((unsigned)__bfloat16_as_ushort(b3) << 16) | __bfloat16_as_ushort(b2);
    wlo.x = pkbf(acc.x - __bfloat162float(b0), acc.y - __bfloat162float(b1));
    wlo.y = pkbf(acc.z - __bfloat162float(b2), acc.w - __bfloat162float(b3));
    ((uint2*)g_aggb)[(long)warp * 32 + lane] = whi;
    ((uint2*)g_aggs)[(long)warp * 32 + lane] = wlo;
}

// ---------------- mma.sync bf16-split SAGE GEMM, double-buffered -----------
// K=32 per stage, 24 stages (6 segments x 4). Tiles: 128 rows x 32 bf16 with
// PADDED 80B row stride -> conflict-free fragment LDS without swizzle.
// cp.async stage s+1 overlaps compute of stage s (wait_group 1).
#define TILE_BYTES (128 * 80)
__global__ void __launch_bounds__(256, 2)
mma_gemm_kernel(const float* __restrict__ bl, int n, int layer,
                const float* __restrict__ Wout,
                const float* __restrict__ bout,
                float* __restrict__ out) {
    __shared__ __align__(16) char sA[2 * TILE_BYTES];
    __shared__ __align__(16) char sW[2 * TILE_BYTES];
    __shared__ float sbias[128];
    __shared__ float swout[128];
    __shared__ float sdot[128];

    const int tid = threadIdx.x;
    const int wid = tid >> 5, lid = tid & 31;
    const int grp = lid >> 2, tg = lid & 3;
    const int wm = (wid & 3) * 32;
    const int wn = (wid >> 2) * 64;
    const int row0 = blockIdx.x * 128;

    const unsigned int sA_addr = (unsigned int)__cvta_generic_to_shared(sA);
    const unsigned int sW_addr = (unsigned int)__cvta_generic_to_shared(sW);

    const __nv_bfloat16* Bb = layer ? g_h1b : g_xb;
    const __nv_bfloat16* Bs = layer ? g_h1s : g_xs;
    const __nv_bfloat16* Wlb = g_Wb + (layer ? 2 : 0) * 16384;
    const __nv_bfloat16* Wls = g_Ws + (layer ? 2 : 0) * 16384;
    const __nv_bfloat16* Wrb = g_Wb + (layer ? 3 : 1) * 16384;
    const __nv_bfloat16* Wrs = g_Ws + (layer ? 3 : 1) * 16384;

    if (tid < 128) {
        sbias[tid] = bl[tid];
        sdot[tid] = 0.f;
        if (layer) swout[tid] = Wout[tid];
    }

    const __nv_bfloat16* Aseq[6] = { g_aggb, g_aggs, g_aggb, Bb, Bs, Bb };
    const __nv_bfloat16* Wseq[6] = { Wlb, Wlb, Wls, Wrb, Wrb, Wrs };

    float acc[2][8][4];
#pragma unroll
    for (int mt = 0; mt < 2; mt++)
#pragma unroll
        for (int nt = 0; nt < 8; nt++)
#pragma unroll
            for (int q = 0; q < 4; q++) acc[mt][nt][q] = 0.f;

    // per-thread fill slots: id = tid + u*256 -> r = id>>2 (0..127), c = id&3
    const int fr0 = tid >> 2,          fc0 = (tid & 3) * 16;        // chunk byte off
    const int fr1 = (tid + 256) >> 2,  fc1 = fc0;
    const int gsrc0 = (fc0 >> 1);  // 16B = 8 bf16 -> element offset = c*8
    const int gsrc1 = (fc1 >> 1);

    // stage s: seg = s>>2, k0 = (s&3)*32
    #define GLOAD(sidx, buf)                                                    \
    do {                                                                        \
        int _seg = (sidx) >> 2;                                                 \
        int _k0 = ((sidx) & 3) * 32;                                            \
        const __nv_bfloat16* _Ap = Aseq[_seg];                                  \
        const __nv_bfloat16* _Wp = Wseq[_seg];                                  \
        int _g0 = row0 + fr0, _g1 = row0 + fr1;                                 \
        cp_async16z(sA_addr + (buf) * TILE_BYTES + fr0 * 80 + fc0,              \
                    _Ap + (long)((_g0 < n) ? _g0 : 0) * 128 + _k0 + gsrc0,      \
                    (_g0 < n) ? 16 : 0);                                        \
        cp_async16z(sA_addr + (buf) * TILE_BYTES + fr1 * 80 + fc1,              \
                    _Ap + (long)((_g1 < n) ? _g1 : 0) * 128 + _k0 + gsrc1,      \
                    (_g1 < n) ? 16 : 0);                                        \
        cp_async16(sW_addr + (buf) * TILE_BYTES + fr0 * 80 + fc0,               \
                   _Wp + fr0 * 128 + _k0 + gsrc0);                              \
        cp_async16(sW_addr + (buf) * TILE_BYTES + fr1 * 80 + fc1,               \
                   _Wp + fr1 * 128 + _k0 + gsrc1);                              \
        cp_commit();                                                            \
    } while (0)

    GLOAD(0, 0);

    for (int s = 0; s < 24; s++) {
        const int buf = s & 1;
        if (s < 23) {
            GLOAD(s + 1, buf ^ 1);
            cp_wait1();
        } else {
            cp_wait0();
        }
        __syncthreads();

        const unsigned int aBase = sA_addr + buf * TILE_BYTES;
        const unsigned int wBase = sW_addr + buf * TILE_BYTES;
#pragma unroll
        for (int ks = 0; ks < 2; ks++) {
            const int kw0 = ks * 8;
            unsigned int a[2][4], b[8][2];
#pragma unroll
            for (int mt = 0; mt < 2; mt++) {
                int rb = wm + mt * 16 + grp;
#pragma unroll
                for (int q = 0; q < 4; q++) {
                    int r = rb + ((q & 1) ? 8 : 0);
                    int kw = kw0 + ((q >> 1) ? 4 : 0) + tg;
                    unsigned int addr = aBase + r * 80 + kw * 4;
                    asm volatile("ld.shared.b32 %0, [%1];"
                                 : "=r"(a[mt][q]) : "r"(addr));
                }
            }
#pragma unroll
            for (int nt = 0; nt < 8; nt++) {
                int nr = wn + nt * 8 + grp;
#pragma unroll
                for (int q = 0; q < 2; q++) {
                    int kw = kw0 + (q ? 4 : 0) + tg;
                    unsigned int addr = wBase + nr * 80 + kw * 4;
                    asm volatile("ld.shared.b32 %0, [%1];"
                                 : "=r"(b[nt][q]) : "r"(addr));
                }
            }
#pragma unroll
            for (int mt = 0; mt < 2; mt++)
#pragma unroll
                for (int nt = 0; nt < 8; nt++)
                    mma16816(acc[mt][nt], a[mt], b[nt]);
        }
        __syncthreads();
    }

    // epilogue: bias + relu; layer 0 -> h1 splits/mirror; layer 1 -> head dot
#pragma unroll
    for (int mt = 0; mt < 2; mt++) {
#pragma unroll
        for (int rr = 0; rr < 2; rr++) {
            int lrow = wm + mt * 16 + grp + rr * 8;
            int gr = row0 + lrow;
            float part = 0.f;
#pragma unroll
            for (int nt = 0; nt < 8; nt++) {
                int col = wn + nt * 8 + tg * 2;
                float v0 = acc[mt][nt][rr * 2 + 0] + sbias[col];
                float v1 = acc[mt][nt][rr * 2 + 1] + sbias[col + 1];
                v0 = v0 > 0.f ? v0 : 0.f;
                v1 = v1 > 0.f ? v1 : 0.f;
                if (layer) {
                    part += v0 * swout[col] + v1 * swout[col + 1];
                } else if (gr < n) {
                    __nv_bfloat16 h0 = __float2bfloat16(v0);
                    __nv_bfloat16 h1v = __float2bfloat16(v1);
                    unsigned int hi = ((unsigned)__bfloat16_as_ushort(h1v) << 16) |
                                      __bfloat16_as_ushort(h0);
                    unsigned int lo = pkbf(v0 - __bfloat162float(h0),
                                           v1 - __bfloat162float(h1v));
                    *(unsigned int*)&g_h1b[(long)gr * 128 + col] = hi;
                    *(unsigned int*)&g_h1s[(long)gr * 128 + col] = lo;
                    __half2 hh = __floats2half2_rn(v0, v1);
                    *(unsigned int*)&g_h1h[(long)gr * 128 + col] =
                        *(unsigned int*)&hh;
                }
            }
            if (layer) {
                part += __shfl_xor_sync(0xffffffffu, part, 1);
                part += __shfl_xor_sync(0xffffffffu, part, 2);
                if (tg == 0 && gr < n) atomicAdd(&sdot[lrow], part);
            }
        }
    }
    if (layer) {
        __syncthreads();
        if (tid < 128) {
            int gr = row0 + tid;
            if (gr < n) out[gr] = sdot[tid] + bout[0];
        }
    }
}

// ---------------- launch ---------------------------------------------------
extern "C" void kernel_launch(void* const* d_in, const int* in_sizes, int n_in,
                              void* d_out, int out_size) {
    const float* x    = (const float*)d_in[0];
    const void*  ei   = d_in[1];
    const float* W1l  = (const float*)d_in[2];
    const float* b1l  = (const float*)d_in[3];
    const float* W1r  = (const float*)d_in[4];
    const float* W2l  = (const float*)d_in[5];
    const float* b2l  = (const float*)d_in[6];
    const float* W2r  = (const float*)d_in[7];
    const float* Wout = (const float*)d_in[8];
    const float* bout = (const float*)d_in[9];
    float*       out  = (float*)d_out;

    const int n = in_sizes[0] / D;    // 50000
    const int E = in_sizes[1] / 2;    // 800000
    const int nb = (n + 1023) / 1024;

    // --- prep + CSR build ---
    prep_kernel<<<(n * 32 + 255) / 256, 256>>>((const int*)ei, (const float4*)x,
                                               W1l, W1r, W2l, W2r, n);
    hist_kernel<<<(E + 255) / 256, 256>>>(ei, E);
    scan_lookback_kernel<<<nb, 256>>>(n, nb);
    scatter_kernel<<<(E + 255) / 256, 256>>>(ei, E);

    const int aggBlocks  = (n * 32 + 255) / 256;
    const int gemmBlocks = (n + 127) / 128;

    // --- layer 1 ---
    aggregate_kernel<<<aggBlocks, 256>>>(n, 0);
    mma_gemm_kernel<<<gemmBlocks, 256>>>(b1l, n, 0, Wout, bout, out);

    // --- layer 2 (head fused) ---
    aggregate_kernel<<<aggBlocks, 256>>>(n, 1);
    mma_gemm_kernel<<<gemmBlocks, 256>>>(b2l, n, 1, Wout, bout, out);
}

// round 14
// speedup vs baseline: 1.0023x; 1.0023x over previous
#include <cuda_runtime.h>
#include <cuda_bf16.h>
#include <cuda_fp16.h>

#define N_NODES 50000
#define N_EDGES 800000
#define D 128

// ---------------- device scratch (no runtime allocation allowed) ----------
__device__ int   g_deg[N_NODES];
__device__ int   g_rowptr[N_NODES + 1];
__device__ int   g_fill[N_NODES];
__device__ int   g_col[N_EDGES];
__device__ int   g_not64;
__device__ int   g_blk_agg[64];
__device__ int   g_blk_incl[64];
__device__ int   g_blk_flag[64];

__device__ __nv_bfloat16 g_aggb[N_NODES * D];
__device__ __nv_bfloat16 g_aggs[N_NODES * D];
__device__ __nv_bfloat16 g_xb[N_NODES * D];
__device__ __nv_bfloat16 g_xs[N_NODES * D];
__device__ __half        g_xh[N_NODES * D];    // fp16 mirror for gather
__device__ __nv_bfloat16 g_h1b[N_NODES * D];
__device__ __nv_bfloat16 g_h1s[N_NODES * D];
__device__ __half        g_h1h[N_NODES * D];   // fp16 mirror of h1
__device__ __nv_bfloat16 g_Wb[4 * 128 * 128];  // Wt hi: [mat][n][k]
__device__ __nv_bfloat16 g_Ws[4 * 128 * 128];  // Wt lo

// ---------------- helpers ---------------------------------------------------
__device__ __forceinline__ unsigned int pkbf(float a, float b) {
    __nv_bfloat16 ha = __float2bfloat16(a), hb = __float2bfloat16(b);
    return ((unsigned int)__bfloat16_as_ushort(hb) << 16) |
           (unsigned int)__bfloat16_as_ushort(ha);
}

__device__ __forceinline__ void cp_async16(unsigned int dst, const void* src) {
    asm volatile("cp.async.ca.shared.global [%0], [%1], 16;"
                 :: "r"(dst), "l"(src) : "memory");
}
__device__ __forceinline__ void cp_async16z(unsigned int dst, const void* src, int sz) {
    asm volatile("cp.async.ca.shared.global [%0], [%1], 16, %2;"
                 :: "r"(dst), "l"(src), "r"(sz) : "memory");
}
__device__ __forceinline__ void cp_commit() {
    asm volatile("cp.async.commit_group;" ::: "memory");
}
__device__ __forceinline__ void cp_wait0() {
    asm volatile("cp.async.wait_group 0;" ::: "memory");
}
__device__ __forceinline__ void cp_wait1() {
    asm volatile("cp.async.wait_group 1;" ::: "memory");
}

// bf16 m16n8k16 row.col mma, fp32 accumulate
__device__ __forceinline__ void mma16816(float* d, const unsigned int* a,
                                         const unsigned int* b) {
    asm volatile(
        "mma.sync.aligned.m16n8k16.row.col.f32.bf16.bf16.f32 "
        "{%0,%1,%2,%3}, {%4,%5,%6,%7}, {%8,%9}, {%0,%1,%2,%3};"
        : "+f"(d[0]), "+f"(d[1]), "+f"(d[2]), "+f"(d[3])
        : "r"(a[0]), "r"(a[1]), "r"(a[2]), "r"(a[3]), "r"(b[0]), "r"(b[1]));
}

// ---------------- prep: zero + dtype probe + weight & x conversion ---------
__global__ void prep_kernel(const int* __restrict__ ei32,
                            const float4* __restrict__ x,
                            const float* __restrict__ W1l,
                            const float* __restrict__ W1r,
                            const float* __restrict__ W2l,
                            const float* __restrict__ W2r,
                            int n) {
    int i = blockIdx.x * blockDim.x + threadIdx.x;
    if (i < n) g_deg[i] = 0;
    if (i < 64) g_blk_flag[i] = 0;
    if (blockIdx.x == 0) {
        if (threadIdx.x == 0) g_not64 = 0;
        __syncthreads();
        if (threadIdx.x < 256 && ei32[2 * threadIdx.x + 1] != 0)
            atomicOr(&g_not64, 1);
    }
    if (i < 4 * 16384) {
        int m = i >> 14;
        int t = i & 16383;
        int nn = t >> 7, kk = t & 127;
        const float* W = (m == 0) ? W1l : (m == 1) ? W1r : (m == 2) ? W2l : W2r;
        float f = W[kk * 128 + nn];
        __nv_bfloat16 hb = __float2bfloat16(f);
        g_Wb[m * 16384 + nn * 128 + kk] = hb;
        g_Ws[m * 16384 + nn * 128 + kk] =
            __float2bfloat16(f - __bfloat162float(hb));
    }
    if (i < n * 32) {
        float4 v = x[i];
        __nv_bfloat16 b0 = __float2bfloat16(v.x), b1 = __float2bfloat16(v.y);
        __nv_bfloat16 b2 = __float2bfloat16(v.z), b3 = __float2bfloat16(v.w);
        uint2 whi, wlo;
        whi.x = ((unsigned)__bfloat16_as_ushort(b1) << 16) | __bfloat16_as_ushort(b0);
        whi.y = ((unsigned)__bfloat16_as_ushort(b3) << 16) | __bfloat16_as_ushort(b2);
        wlo.x = pkbf(v.x - __bfloat162float(b0), v.y - __bfloat162float(b1));
        wlo.y = pkbf(v.z - __bfloat162float(b2), v.w - __bfloat162float(b3));
        ((uint2*)g_xb)[i] = whi;
        ((uint2*)g_xs)[i] = wlo;
        __half2 h01 = __floats2half2_rn(v.x, v.y);
        __half2 h23 = __floats2half2_rn(v.z, v.w);
        ((uint2*)g_xh)[i] = make_uint2(*(unsigned int*)&h01, *(unsigned int*)&h23);
    }
}

__global__ void hist_kernel(const void* __restrict__ eiv, int E) {
    int e = blockIdx.x * blockDim.x + threadIdx.x;
    if (e >= E) return;
    int d;
    if (g_not64) d = ((const int*)eiv)[E + e];
    else         d = (int)((const long long*)eiv)[E + e];
    atomicAdd(&g_deg[d], 1);
}

__global__ void scan_lookback_kernel(int n, int nb) {
    const int b = blockIdx.x;
    const int t = threadIdx.x;
    const int lane = t & 31, wid = t >> 5;
    int i0 = b * 1024 + t * 4;

    int vals[4]; int local = 0;
#pragma unroll
    for (int u = 0; u < 4; u++) {
        int i = i0 + u;
        vals[u] = (i < n) ? g_deg[i] : 0;
        local += vals[u];
    }
    int incl = local;
#pragma unroll
    for (int off = 1; off < 32; off <<= 1) {
        int u = __shfl_up_sync(0xffffffffu, incl, off);
        if (lane >= off) incl += u;
    }
    __shared__ int ws[8], wexcl[8];
    __shared__ int s_prefix;
    if (lane == 31) ws[wid] = incl;
    __syncthreads();
    if (t < 8) {
        int s = ws[t];
        int si = s;
#pragma unroll
        for (int off = 1; off < 8; off <<= 1) {
            int u = __shfl_up_sync(0xffu, si, off);
            if (t >= off) si += u;
        }
        wexcl[t] = si - s;
    }
    __syncthreads();
    const int total = wexcl[7] + ws[7];

    if (t == 0) {
        g_blk_agg[b] = total;
        __threadfence();
        ((volatile int*)g_blk_flag)[b] = 1;
    }
    if (wid == 0) {
        int prefix = 0;
        int j = b - 1;
        while (j >= 0) {
            int jj = j - lane;
            int f = 0, v = 0;
            if (jj >= 0) {
                do { f = ((volatile int*)g_blk_flag)[jj]; } while (f == 0);
                __threadfence();
                v = (f == 2) ? ((volatile int*)g_blk_incl)[jj]
                             : ((volatile int*)g_blk_agg)[jj];
            }
            unsigned done = __ballot_sync(0xffffffffu, jj >= 0 && f == 2);
            if (done) {
                int fl = __ffs(done) - 1;
                int contrib = (lane <= fl) ? v : 0;
#pragma unroll
                for (int off = 16; off; off >>= 1)
                    contrib += __shfl_xor_sync(0xffffffffu, contrib, off);
                prefix += contrib;
                break;
            } else {
                int contrib = (jj >= 0) ? v : 0;
#pragma unroll
                for (int off = 16; off; off >>= 1)
                    contrib += __shfl_xor_sync(0xffffffffu, contrib, off);
                prefix += contrib;
                j -= 32;
            }
        }
        if (lane == 0) {
            g_blk_incl[b] = prefix + total;
            __threadfence();
            ((volatile int*)g_blk_flag)[b] = 2;
            s_prefix = prefix;
            if (b == nb - 1) g_rowptr[n] = prefix + total;
        }
    }
    __syncthreads();

    int excl = s_prefix + wexcl[wid] + (incl - local);
#pragma unroll
    for (int u = 0; u < 4; u++) {
        int i = i0 + u;
        if (i < n) { g_rowptr[i] = excl; g_fill[i] = excl; }
        excl += vals[u];
    }
}

__global__ void scatter_kernel(const void* __restrict__ eiv, int E) {
    int e = blockIdx.x * blockDim.x + threadIdx.x;
    if (e >= E) return;
    int s, d;
    if (g_not64) {
        s = ((const int*)eiv)[e];
        d = ((const int*)eiv)[E + e];
    } else {
        s = (int)((const long long*)eiv)[e];
        d = (int)((const long long*)eiv)[E + e];
    }
    int pos = atomicAdd(&g_fill[d], 1);
    g_col[pos] = s;
}

// ---------------- mean aggregation: warp/node, unroll 8 --------------------
__global__ void aggregate_kernel(int n, int use_h1) {
    int warp = (blockIdx.x * blockDim.x + threadIdx.x) >> 5;
    int lane = threadIdx.x & 31;
    if (warp >= n) return;
    const uint2* __restrict__ src =
        use_h1 ? (const uint2*)g_h1h : (const uint2*)g_xh;
    int beg = g_rowptr[warp];
    int end = g_rowptr[warp + 1];
    float4 acc = make_float4(0.f, 0.f, 0.f, 0.f);
    int e = beg;
    for (; e + 8 <= end; e += 8) {
        int s0 = g_col[e],     s1 = g_col[e + 1], s2 = g_col[e + 2], s3 = g_col[e + 3];
        int s4 = g_col[e + 4], s5 = g_col[e + 5], s6 = g_col[e + 6], s7 = g_col[e + 7];
        uint2 v0 = src[(long)s0 * 32 + lane];
        uint2 v1 = src[(long)s1 * 32 + lane];
        uint2 v2 = src[(long)s2 * 32 + lane];
        uint2 v3 = src[(long)s3 * 32 + lane];
        uint2 v4 = src[(long)s4 * 32 + lane];
        uint2 v5 = src[(long)s5 * 32 + lane];
        uint2 v6 = src[(long)s6 * 32 + lane];
        uint2 v7 = src[(long)s7 * 32 + lane];
#pragma unroll
        for (int q = 0; q < 8; q++) {
            uint2 v = (q == 0) ? v0 : (q == 1) ? v1 : (q == 2) ? v2 : (q == 3) ? v3
                    : (q == 4) ? v4 : (q == 5) ? v5 : (q == 6) ? v6 : v7;
            float2 f0 = __half22float2(*(__half2*)&v.x);
            float2 f1 = __half22float2(*(__half2*)&v.y);
            acc.x += f0.x; acc.y += f0.y; acc.z += f1.x; acc.w += f1.y;
        }
    }
    for (; e + 4 <= end; e += 4) {
        int s0 = g_col[e], s1 = g_col[e + 1], s2 = g_col[e + 2], s3 = g_col[e + 3];
        uint2 v0 = src[(long)s0 * 32 + lane];
        uint2 v1 = src[(long)s1 * 32 + lane];
        uint2 v2 = src[(long)s2 * 32 + lane];
        uint2 v3 = src[(long)s3 * 32 + lane];
#pragma unroll
        for (int q = 0; q < 4; q++) {
            uint2 v = (q == 0) ? v0 : (q == 1) ? v1 : (q == 2) ? v2 : v3;
            float2 f0 = __half22float2(*(__half2*)&v.x);
            float2 f1 = __half22float2(*(__half2*)&v.y);
            acc.x += f0.x; acc.y += f0.y; acc.z += f1.x; acc.w += f1.y;
        }
    }
    for (; e < end; ++e) {
        int s = g_col[e];
        uint2 v = src[(long)s * 32 + lane];
        float2 f0 = __half22float2(*(__half2*)&v.x);
        float2 f1 = __half22float2(*(__half2*)&v.y);
        acc.x += f0.x; acc.y += f0.y; acc.z += f1.x; acc.w += f1.y;
    }
    int deg = end - beg;
    float sc = 1.0f / (float)(deg > 0 ? deg : 1);
    acc.x *= sc; acc.y *= sc; acc.z *= sc; acc.w *= sc;

    __nv_bfloat16 b0 = __float2bfloat16(acc.x), b1 = __float2bfloat16(acc.y);
    __nv_bfloat16 b2 = __float2bfloat16(acc.z), b3 = __float2bfloat16(acc.w);
    uint2 whi, wlo;
    whi.x = ((unsigned)__bfloat16_as_ushort(b1) << 16) | __bfloat16_as_ushort(b0);
    whi.y = ((unsigned)__bfloat16_as_ushort(b3) << 16) | __bfloat16_as_ushort(b2);
    wlo.x = pkbf(acc.x - __bfloat162float(b0), acc.y - __bfloat162float(b1));
    wlo.y = pkbf(acc.z - __bfloat162float(b2), acc.w - __bfloat162float(b3));
    ((uint2*)g_aggb)[(long)warp * 32 + lane] = whi;
    ((uint2*)g_aggs)[(long)warp * 32 + lane] = wlo;
}

// ---------------- mma.sync bf16-split SAGE GEMM, double-buffered -----------
// K=32 per stage, 24 stages (6 segments x 4). Tiles: 128 rows x 32 bf16 with
// PADDED 80B row stride -> conflict-free fragment LDS without swizzle.
// cp.async stage s+1 overlaps compute of stage s (wait_group 1).
#define TILE_BYTES (128 * 80)
__global__ void __launch_bounds__(256, 2)
mma_gemm_kernel(const float* __restrict__ bl, int n, int layer,
                const float* __restrict__ Wout,
                const float* __restrict__ bout,
                float* __restrict__ out) {
    __shared__ __align__(16) char sA[2 * TILE_BYTES];
    __shared__ __align__(16) char sW[2 * TILE_BYTES];
    __shared__ float sbias[128];
    __shared__ float swout[128];
    __shared__ float sdot[128];

    const int tid = threadIdx.x;
    const int wid = tid >> 5, lid = tid & 31;
    const int grp = lid >> 2, tg = lid & 3;
    const int wm = (wid & 3) * 32;
    const int wn = (wid >> 2) * 64;
    const int row0 = blockIdx.x * 128;

    const unsigned int sA_addr = (unsigned int)__cvta_generic_to_shared(sA);
    const unsigned int sW_addr = (unsigned int)__cvta_generic_to_shared(sW);

    const __nv_bfloat16* Bb = layer ? g_h1b : g_xb;
    const __nv_bfloat16* Bs = layer ? g_h1s : g_xs;
    const __nv_bfloat16* Wlb = g_Wb + (layer ? 2 : 0) * 16384;
    const __nv_bfloat16* Wls = g_Ws + (layer ? 2 : 0) * 16384;
    const __nv_bfloat16* Wrb = g_Wb + (layer ? 3 : 1) * 16384;
    const __nv_bfloat16* Wrs = g_Ws + (layer ? 3 : 1) * 16384;

    if (tid < 128) {
        sbias[tid] = bl[tid];
        sdot[tid] = 0.f;
        if (layer) swout[tid] = Wout[tid];
    }

    const __nv_bfloat16* Aseq[6] = { g_aggb, g_aggs, g_aggb, Bb, Bs, Bb };
    const __nv_bfloat16* Wseq[6] = { Wlb, Wlb, Wls, Wrb, Wrb, Wrs };

    float acc[2][8][4];
#pragma unroll
    for (int mt = 0; mt < 2; mt++)
#pragma unroll
        for (int nt = 0; nt < 8; nt++)
#pragma unroll
            for (int q = 0; q < 4; q++) acc[mt][nt][q] = 0.f;

    // per-thread fill slots: id = tid + u*256 -> r = id>>2 (0..127), c = id&3
    const int fr0 = tid >> 2,          fc0 = (tid & 3) * 16;        // chunk byte off
    const int fr1 = (tid + 256) >> 2,  fc1 = fc0;
    const int gsrc0 = (fc0 >> 1);  // 16B = 8 bf16 -> element offset = c*8
    const int gsrc1 = (fc1 >> 1);

    // stage s: seg = s>>2, k0 = (s&3)*32
    #define GLOAD(sidx, buf)                                                    \
    do {                                                                        \
        int _seg = (sidx) >> 2;                                                 \
        int _k0 = ((sidx) & 3) * 32;                                            \
        const __nv_bfloat16* _Ap = Aseq[_seg];                                  \
        const __nv_bfloat16* _Wp = Wseq[_seg];                                  \
        int _g0 = row0 + fr0, _g1 = row0 + fr1;                                 \
        cp_async16z(sA_addr + (buf) * TILE_BYTES + fr0 * 80 + fc0,              \
                    _Ap + (long)((_g0 < n) ? _g0 : 0) * 128 + _k0 + gsrc0,      \
                    (_g0 < n) ? 16 : 0);                                        \
        cp_async16z(sA_addr + (buf) * TILE_BYTES + fr1 * 80 + fc1,              \
                    _Ap + (long)((_g1 < n) ? _g1 : 0) * 128 + _k0 + gsrc1,      \
                    (_g1 < n) ? 16 : 0);                                        \
        cp_async16(sW_addr + (buf) * TILE_BYTES + fr0 * 80 + fc0,               \
                   _Wp + fr0 * 128 + _k0 + gsrc0);                              \
        cp_async16(sW_addr + (buf) * TILE_BYTES + fr1 * 80 + fc1,               \
                   _Wp + fr1 * 128 + _k0 + gsrc1);                              \
        cp_commit();                                                            \
    } while (0)

    GLOAD(0, 0);

    for (int s = 0; s < 24; s++) {
        const int buf = s & 1;
        if (s < 23) {
            GLOAD(s + 1, buf ^ 1);
            cp_wait1();
        } else {
            cp_wait0();
        }
        __syncthreads();

        const unsigned int aBase = sA_addr + buf * TILE_BYTES;
        const unsigned int wBase = sW_addr + buf * TILE_BYTES;
#pragma unroll
        for (int ks = 0; ks < 2; ks++) {
            const int kw0 = ks * 8;
            unsigned int a[2][4], b[8][2];
#pragma unroll
            for (int mt = 0; mt < 2; mt++) {
                int rb = wm + mt * 16 + grp;
#pragma unroll
                for (int q = 0; q < 4; q++) {
                    int r = rb + ((q & 1) ? 8 : 0);
                    int kw = kw0 + ((q >> 1) ? 4 : 0) + tg;
                    unsigned int addr = aBase + r * 80 + kw * 4;
                    asm volatile("ld.shared.b32 %0, [%1];"
                                 : "=r"(a[mt][q]) : "r"(addr));
                }
            }
#pragma unroll
            for (int nt = 0; nt < 8; nt++) {
                int nr = wn + nt * 8 + grp;
#pragma unroll
                for (int q = 0; q < 2; q++) {
                    int kw = kw0 + (q ? 4 : 0) + tg;
                    unsigned int addr = wBase + nr * 80 + kw * 4;
                    asm volatile("ld.shared.b32 %0, [%1];"
                                 : "=r"(b[nt][q]) : "r"(addr));
                }
            }
#pragma unroll
            for (int mt = 0; mt < 2; mt++)
#pragma unroll
                for (int nt = 0; nt < 8; nt++)
                    mma16816(acc[mt][nt], a[mt], b[nt]);
        }
        __syncthreads();
    }

    // epilogue: bias + relu; layer 0 -> h1 splits/mirror; layer 1 -> head dot
#pragma unroll
    for (int mt = 0; mt < 2; mt++) {
#pragma unroll
        for (int rr = 0; rr < 2; rr++) {
            int lrow = wm + mt * 16 + grp + rr * 8;
            int gr = row0 + lrow;
            float part = 0.f;
#pragma unroll
            for (int nt = 0; nt < 8; nt++) {
                int col = wn + nt * 8 + tg * 2;
                float v0 = acc[mt][nt][rr * 2 + 0] + sbias[col];
                float v1 = acc[mt][nt][rr * 2 + 1] + sbias[col + 1];
                v0 = v0 > 0.f ? v0 : 0.f;
                v1 = v1 > 0.f ? v1 : 0.f;
                if (layer) {
                    part += v0 * swout[col] + v1 * swout[col + 1];
                } else if (gr < n) {
                    __nv_bfloat16 h0 = __float2bfloat16(v0);
                    __nv_bfloat16 h1v = __float2bfloat16(v1);
                    unsigned int hi = ((unsigned)__bfloat16_as_ushort(h1v) << 16) |
                                      __bfloat16_as_ushort(h0);
                    unsigned int lo = pkbf(v0 - __bfloat162float(h0),
                                           v1 - __bfloat162float(h1v));
                    *(unsigned int*)&g_h1b[(long)gr * 128 + col] = hi;
                    *(unsigned int*)&g_h1s[(long)gr * 128 + col] = lo;
                    __half2 hh = __floats2half2_rn(v0, v1);
                    *(unsigned int*)&g_h1h[(long)gr * 128 + col] =
                        *(unsigned int*)&hh;
                }
            }
            if (layer) {
                part += __shfl_xor_sync(0xffffffffu, part, 1);
                part += __shfl_xor_sync(0xffffffffu, part, 2);
                if (tg == 0 && gr < n) atomicAdd(&sdot[lrow], part);
            }
        }
    }
    if (layer) {
        __syncthreads();
        if (tid < 128) {
            int gr = row0 + tid;
            if (gr < n) out[gr] = sdot[tid] + bout[0];
        }
    }
}

// ---------------- launch ---------------------------------------------------
extern "C" void kernel_launch(void* const* d_in, const int* in_sizes, int n_in,
                              void* d_out, int out_size) {
    const float* x    = (const float*)d_in[0];
    const void*  ei   = d_in[1];
    const float* W1l  = (const float*)d_in[2];
    const float* b1l  = (const float*)d_in[3];
    const float* W1r  = (const float*)d_in[4];
    const float* W2l  = (const float*)d_in[5];
    const float* b2l  = (const float*)d_in[6];
    const float* W2r  = (const float*)d_in[7];
    const float* Wout = (const float*)d_in[8];
    const float* bout = (const float*)d_in[9];
    float*       out  = (float*)d_out;

    const int n = in_sizes[0] / D;    // 50000
    const int E = in_sizes[1] / 2;    // 800000
    const int nb = (n + 1023) / 1024;

    // --- prep + CSR build ---
    prep_kernel<<<(n * 32 + 255) / 256, 256>>>((const int*)ei, (const float4*)x,
                                               W1l, W1r, W2l, W2r, n);
    hist_kernel<<<(E + 255) / 256, 256>>>(ei, E);
    scan_lookback_kernel<<<nb, 256>>>(n, nb);
    scatter_kernel<<<(E + 255) / 256, 256>>>(ei, E);

    const int aggBlocks  = (n * 32 + 255) / 256;
    const int gemmBlocks = (n + 127) / 128;

    // --- layer 1 ---
    aggregate_kernel<<<aggBlocks, 256>>>(n, 0);
    mma_gemm_kernel<<<gemmBlocks, 256>>>(b1l, n, 0, Wout, bout, out);

    // --- layer 2 (head fused) ---
    aggregate_kernel<<<aggBlocks, 256>>>(n, 1);
    mma_gemm_kernel<<<gemmBlocks, 256>>>(b2l, n, 1, Wout, bout, out);
}

// round 15
// speedup vs baseline: 1.0492x; 1.0468x over previous
#include <cuda_runtime.h>
#include <cuda_bf16.h>
#include <cuda_fp16.h>

#define N_NODES 50000
#define N_EDGES 800000
#define D 128

// ---------------- device scratch (no runtime allocation allowed) ----------
__device__ int   g_deg[N_NODES];
__device__ int   g_rowptr[N_NODES + 1];
__device__ int   g_fill[N_NODES];
__device__ int   g_col[N_EDGES];
__device__ int   g_not64;
__device__ int   g_blk_agg[64];
__device__ int   g_blk_incl[64];
__device__ int   g_blk_flag[64];

__device__ __nv_bfloat16 g_aggb[N_NODES * D];
__device__ __nv_bfloat16 g_aggs[N_NODES * D];
__device__ __nv_bfloat16 g_xb[N_NODES * D];
__device__ __nv_bfloat16 g_xs[N_NODES * D];
__device__ __half        g_xh[N_NODES * D];    // fp16 mirror for gather
__device__ __nv_bfloat16 g_h1b[N_NODES * D];
__device__ __nv_bfloat16 g_h1s[N_NODES * D];
__device__ __half        g_h1h[N_NODES * D];   // fp16 mirror of h1
__device__ __nv_bfloat16 g_Wb[4 * 128 * 128];  // Wt hi: [mat][n][k]
__device__ __nv_bfloat16 g_Ws[4 * 128 * 128];  // Wt lo

// ---------------- helpers ---------------------------------------------------
__device__ __forceinline__ unsigned int pkbf(float a, float b) {
    __nv_bfloat16 ha = __float2bfloat16(a), hb = __float2bfloat16(b);
    return ((unsigned int)__bfloat16_as_ushort(hb) << 16) |
           (unsigned int)__bfloat16_as_ushort(ha);
}

__device__ __forceinline__ void cp_async16(unsigned int dst, const void* src) {
    asm volatile("cp.async.ca.shared.global [%0], [%1], 16;"
                 :: "r"(dst), "l"(src) : "memory");
}
__device__ __forceinline__ void cp_async16z(unsigned int dst, const void* src, int sz) {
    asm volatile("cp.async.ca.shared.global [%0], [%1], 16, %2;"
                 :: "r"(dst), "l"(src), "r"(sz) : "memory");
}
__device__ __forceinline__ void cp_commit() {
    asm volatile("cp.async.commit_group;" ::: "memory");
}
__device__ __forceinline__ void cp_wait0() {
    asm volatile("cp.async.wait_group 0;" ::: "memory");
}

// bf16 m16n8k16 row.col mma, fp32 accumulate
__device__ __forceinline__ void mma16816(float* d, const unsigned int* a,
                                         const unsigned int* b) {
    asm volatile(
        "mma.sync.aligned.m16n8k16.row.col.f32.bf16.bf16.f32 "
        "{%0,%1,%2,%3}, {%4,%5,%6,%7}, {%8,%9}, {%0,%1,%2,%3};"
        : "+f"(d[0]), "+f"(d[1]), "+f"(d[2]), "+f"(d[3])
        : "r"(a[0]), "r"(a[1]), "r"(a[2]), "r"(a[3]), "r"(b[0]), "r"(b[1]));
}

// ---------------- prep: zero + dtype probe + weight & x conversion ---------
__global__ void prep_kernel(const int* __restrict__ ei32,
                            const float4* __restrict__ x,
                            const float* __restrict__ W1l,
                            const float* __restrict__ W1r,
                            const float* __restrict__ W2l,
                            const float* __restrict__ W2r,
                            int n) {
    int i = blockIdx.x * blockDim.x + threadIdx.x;
    if (i < n) g_deg[i] = 0;
    if (i < 64) g_blk_flag[i] = 0;
    if (blockIdx.x == 0) {
        if (threadIdx.x == 0) g_not64 = 0;
        __syncthreads();
        if (threadIdx.x < 256 && ei32[2 * threadIdx.x + 1] != 0)
            atomicOr(&g_not64, 1);
    }
    if (i < 4 * 16384) {
        int m = i >> 14;
        int t = i & 16383;
        int nn = t >> 7, kk = t & 127;
        const float* W = (m == 0) ? W1l : (m == 1) ? W1r : (m == 2) ? W2l : W2r;
        float f = W[kk * 128 + nn];
        __nv_bfloat16 hb = __float2bfloat16(f);
        g_Wb[m * 16384 + nn * 128 + kk] = hb;
        g_Ws[m * 16384 + nn * 128 + kk] =
            __float2bfloat16(f - __bfloat162float(hb));
    }
    if (i < n * 32) {
        float4 v = x[i];
        __nv_bfloat16 b0 = __float2bfloat16(v.x), b1 = __float2bfloat16(v.y);
        __nv_bfloat16 b2 = __float2bfloat16(v.z), b3 = __float2bfloat16(v.w);
        uint2 whi, wlo;
        whi.x = ((unsigned)__bfloat16_as_ushort(b1) << 16) | __bfloat16_as_ushort(b0);
        whi.y = ((unsigned)__bfloat16_as_ushort(b3) << 16) | __bfloat16_as_ushort(b2);
        wlo.x = pkbf(v.x - __bfloat162float(b0), v.y - __bfloat162float(b1));
        wlo.y = pkbf(v.z - __bfloat162float(b2), v.w - __bfloat162float(b3));
        ((uint2*)g_xb)[i] = whi;
        ((uint2*)g_xs)[i] = wlo;
        __half2 h01 = __floats2half2_rn(v.x, v.y);
        __half2 h23 = __floats2half2_rn(v.z, v.w);
        ((uint2*)g_xh)[i] = make_uint2(*(unsigned int*)&h01, *(unsigned int*)&h23);
    }
}

__global__ void hist_kernel(const void* __restrict__ eiv, int E) {
    int e = blockIdx.x * blockDim.x + threadIdx.x;
    if (e >= E) return;
    int d;
    if (g_not64) d = ((const int*)eiv)[E + e];
    else         d = (int)((const long long*)eiv)[E + e];
    atomicAdd(&g_deg[d], 1);
}

__global__ void scan_lookback_kernel(int n, int nb) {
    const int b = blockIdx.x;
    const int t = threadIdx.x;
    const int lane = t & 31, wid = t >> 5;
    int i0 = b * 1024 + t * 4;

    int vals[4]; int local = 0;
#pragma unroll
    for (int u = 0; u < 4; u++) {
        int i = i0 + u;
        vals[u] = (i < n) ? g_deg[i] : 0;
        local += vals[u];
    }
    int incl = local;
#pragma unroll
    for (int off = 1; off < 32; off <<= 1) {
        int u = __shfl_up_sync(0xffffffffu, incl, off);
        if (lane >= off) incl += u;
    }
    __shared__ int ws[8], wexcl[8];
    __shared__ int s_prefix;
    if (lane == 31) ws[wid] = incl;
    __syncthreads();
    if (t < 8) {
        int s = ws[t];
        int si = s;
#pragma unroll
        for (int off = 1; off < 8; off <<= 1) {
            int u = __shfl_up_sync(0xffu, si, off);
            if (t >= off) si += u;
        }
        wexcl[t] = si - s;
    }
    __syncthreads();
    const int total = wexcl[7] + ws[7];

    if (t == 0) {
        g_blk_agg[b] = total;
        __threadfence();
        ((volatile int*)g_blk_flag)[b] = 1;
    }
    if (wid == 0) {
        int prefix = 0;
        int j = b - 1;
        while (j >= 0) {
            int jj = j - lane;
            int f = 0, v = 0;
            if (jj >= 0) {
                do { f = ((volatile int*)g_blk_flag)[jj]; } while (f == 0);
                __threadfence();
                v = (f == 2) ? ((volatile int*)g_blk_incl)[jj]
                             : ((volatile int*)g_blk_agg)[jj];
            }
            unsigned done = __ballot_sync(0xffffffffu, jj >= 0 && f == 2);
            if (done) {
                int fl = __ffs(done) - 1;
                int contrib = (lane <= fl) ? v : 0;
#pragma unroll
                for (int off = 16; off; off >>= 1)
                    contrib += __shfl_xor_sync(0xffffffffu, contrib, off);
                prefix += contrib;
                break;
            } else {
                int contrib = (jj >= 0) ? v : 0;
#pragma unroll
                for (int off = 16; off; off >>= 1)
                    contrib += __shfl_xor_sync(0xffffffffu, contrib, off);
                prefix += contrib;
                j -= 32;
            }
        }
        if (lane == 0) {
            g_blk_incl[b] = prefix + total;
            __threadfence();
            ((volatile int*)g_blk_flag)[b] = 2;
            s_prefix = prefix;
            if (b == nb - 1) g_rowptr[n] = prefix + total;
        }
    }
    __syncthreads();

    int excl = s_prefix + wexcl[wid] + (incl - local);
#pragma unroll
    for (int u = 0; u < 4; u++) {
        int i = i0 + u;
        if (i < n) { g_rowptr[i] = excl; g_fill[i] = excl; }
        excl += vals[u];
    }
}

__global__ void scatter_kernel(const void* __restrict__ eiv, int E) {
    int e = blockIdx.x * blockDim.x + threadIdx.x;
    if (e >= E) return;
    int s, d;
    if (g_not64) {
        s = ((const int*)eiv)[e];
        d = ((const int*)eiv)[E + e];
    } else {
        s = (int)((const long long*)eiv)[e];
        d = (int)((const long long*)eiv)[E + e];
    }
    int pos = atomicAdd(&g_fill[d], 1);
    g_col[pos] = s;
}

// ---------------- mean aggregation: warp/node, unroll 8 (isolated change) --
__global__ void aggregate_kernel(int n, int use_h1) {
    int warp = (blockIdx.x * blockDim.x + threadIdx.x) >> 5;
    int lane = threadIdx.x & 31;
    if (warp >= n) return;
    const uint2* __restrict__ src =
        use_h1 ? (const uint2*)g_h1h : (const uint2*)g_xh;
    int beg = g_rowptr[warp];
    int end = g_rowptr[warp + 1];
    float4 acc = make_float4(0.f, 0.f, 0.f, 0.f);
    int e = beg;
    for (; e + 8 <= end; e += 8) {
        int s0 = g_col[e],     s1 = g_col[e + 1], s2 = g_col[e + 2], s3 = g_col[e + 3];
        int s4 = g_col[e + 4], s5 = g_col[e + 5], s6 = g_col[e + 6], s7 = g_col[e + 7];
        uint2 v0 = src[(long)s0 * 32 + lane];
        uint2 v1 = src[(long)s1 * 32 + lane];
        uint2 v2 = src[(long)s2 * 32 + lane];
        uint2 v3 = src[(long)s3 * 32 + lane];
        uint2 v4 = src[(long)s4 * 32 + lane];
        uint2 v5 = src[(long)s5 * 32 + lane];
        uint2 v6 = src[(long)s6 * 32 + lane];
        uint2 v7 = src[(long)s7 * 32 + lane];
#pragma unroll
        for (int q = 0; q < 8; q++) {
            uint2 v = (q == 0) ? v0 : (q == 1) ? v1 : (q == 2) ? v2 : (q == 3) ? v3
                    : (q == 4) ? v4 : (q == 5) ? v5 : (q == 6) ? v6 : v7;
            float2 f0 = __half22float2(*(__half2*)&v.x);
            float2 f1 = __half22float2(*(__half2*)&v.y);
            acc.x += f0.x; acc.y += f0.y; acc.z += f1.x; acc.w += f1.y;
        }
    }
    for (; e + 4 <= end; e += 4) {
        int s0 = g_col[e], s1 = g_col[e + 1], s2 = g_col[e + 2], s3 = g_col[e + 3];
        uint2 v0 = src[(long)s0 * 32 + lane];
        uint2 v1 = src[(long)s1 * 32 + lane];
        uint2 v2 = src[(long)s2 * 32 + lane];
        uint2 v3 = src[(long)s3 * 32 + lane];
#pragma unroll
        for (int q = 0; q < 4; q++) {
            uint2 v = (q == 0) ? v0 : (q == 1) ? v1 : (q == 2) ? v2 : v3;
            float2 f0 = __half22float2(*(__half2*)&v.x);
            float2 f1 = __half22float2(*(__half2*)&v.y);
            acc.x += f0.x; acc.y += f0.y; acc.z += f1.x; acc.w += f1.y;
        }
    }
    for (; e < end; ++e) {
        int s = g_col[e];
        uint2 v = src[(long)s * 32 + lane];
        float2 f0 = __half22float2(*(__half2*)&v.x);
        float2 f1 = __half22float2(*(__half2*)&v.y);
        acc.x += f0.x; acc.y += f0.y; acc.z += f1.x; acc.w += f1.y;
    }
    int deg = end - beg;
    float sc = 1.0f / (float)(deg > 0 ? deg : 1);
    acc.x *= sc; acc.y *= sc; acc.z *= sc; acc.w *= sc;

    __nv_bfloat16 b0 = __float2bfloat16(acc.x), b1 = __float2bfloat16(acc.y);
    __nv_bfloat16 b2 = __float2bfloat16(acc.z), b3 = __float2bfloat16(acc.w);
    uint2 whi, wlo;
    whi.x = ((unsigned)__bfloat16_as_ushort(b1) << 16) | __bfloat16_as_ushort(b0);
    whi.y = ((unsigned)__bfloat16_as_ushort(b3) << 16) | __bfloat16_as_ushort(b2);
    wlo.x = pkbf(acc.x - __bfloat162float(b0), acc.y - __bfloat162float(b1));
    wlo.y = pkbf(acc.z - __bfloat162float(b2), acc.w - __bfloat162float(b3));
    ((uint2*)g_aggb)[(long)warp * 32 + lane] = whi;
    ((uint2*)g_aggs)[(long)warp * 32 + lane] = wlo;
}

// ---------------- mma.sync bf16-split SAGE GEMM (R12: single-buffer) -------
// layer=0: out -> h1 splits + fp16 mirror.
// layer=1: head fused -- out[row] = relu(h2_row) . Wout + bout.
__global__ void __launch_bounds__(256, 2)
mma_gemm_kernel(const float* __restrict__ bl, int n, int layer,
                const float* __restrict__ Wout,
                const float* __restrict__ bout,
                float* __restrict__ out) {
    __shared__ __align__(16) __nv_bfloat16 sA[128 * 64];
    __shared__ __align__(16) __nv_bfloat16 sW[128 * 64];
    __shared__ float sbias[128];
    __shared__ float swout[128];
    __shared__ float sdot[128];

    const int tid = threadIdx.x;
    const int wid = tid >> 5, lid = tid & 31;
    const int grp = lid >> 2, tg = lid & 3;
    const int wm = (wid & 3) * 32;
    const int wn = (wid >> 2) * 64;
    const int row0 = blockIdx.x * 128;

    const unsigned int sA_addr = (unsigned int)__cvta_generic_to_shared(sA);
    const unsigned int sW_addr = (unsigned int)__cvta_generic_to_shared(sW);

    const __nv_bfloat16* Bb = layer ? g_h1b : g_xb;
    const __nv_bfloat16* Bs = layer ? g_h1s : g_xs;
    const __nv_bfloat16* Wlb = g_Wb + (layer ? 2 : 0) * 16384;
    const __nv_bfloat16* Wls = g_Ws + (layer ? 2 : 0) * 16384;
    const __nv_bfloat16* Wrb = g_Wb + (layer ? 3 : 1) * 16384;
    const __nv_bfloat16* Wrs = g_Ws + (layer ? 3 : 1) * 16384;

    if (tid < 128) {
        sbias[tid] = bl[tid];
        sdot[tid] = 0.f;
        if (layer) swout[tid] = Wout[tid];
    }

    const __nv_bfloat16* Aseq[6] = { g_aggb, g_aggs, g_aggb, Bb, Bs, Bb };
    const __nv_bfloat16* Wseq[6] = { Wlb, Wlb, Wls, Wrb, Wrb, Wrs };

    float acc[2][8][4];
#pragma unroll
    for (int mt = 0; mt < 2; mt++)
#pragma unroll
        for (int nt = 0; nt < 8; nt++)
#pragma unroll
            for (int q = 0; q < 4; q++) acc[mt][nt][q] = 0.f;

    for (int h = 0; h < 12; h++) {
        const int seg = h >> 1;
        const int k0 = (h & 1) * 64;
        const __nv_bfloat16* Ap = Aseq[seg];
        const __nv_bfloat16* Wp = Wseq[seg];

        __syncthreads();
#pragma unroll
        for (int u = 0; u < 4; u++) {
            int id = tid + u * 256;
            int r = id >> 3, c = id & 7;
            int gr = row0 + r;
            unsigned int dst = sA_addr + r * 128 + ((c ^ (r & 7)) * 16);
            const void* src = Ap + (long)((gr < n) ? gr : 0) * 128 + k0 + c * 8;
            cp_async16z(dst, src, (gr < n) ? 16 : 0);
        }
#pragma unroll
        for (int u = 0; u < 4; u++) {
            int id = tid + u * 256;
            int r = id >> 3, c = id & 7;
            unsigned int dst = sW_addr + r * 128 + ((c ^ (r & 7)) * 16);
            cp_async16(dst, Wp + r * 128 + k0 + c * 8);
        }
        cp_commit();
        cp_wait0();
        __syncthreads();

#pragma unroll
        for (int ks = 0; ks < 4; ks++) {
            const int kw0 = ks * 8;
            unsigned int a[2][4], b[8][2];
#pragma unroll
            for (int mt = 0; mt < 2; mt++) {
                int rb = wm + mt * 16 + grp;
#pragma unroll
                for (int q = 0; q < 4; q++) {
                    int r = rb + ((q & 1) ? 8 : 0);
                    int kw = kw0 + ((q >> 1) ? 4 : 0) + tg;
                    unsigned int byte = (unsigned)(r * 128 +
                        (((kw >> 2) ^ (r & 7)) << 4) + (kw & 3) * 4);
                    a[mt][q] = *(const unsigned int*)((const char*)sA + byte);
                }
            }
#pragma unroll
            for (int nt = 0; nt < 8; nt++) {
                int nr = wn + nt * 8 + grp;
#pragma unroll
                for (int q = 0; q < 2; q++) {
                    int kw = kw0 + (q ? 4 : 0) + tg;
                    unsigned int byte = (unsigned)(nr * 128 +
                        (((kw >> 2) ^ (nr & 7)) << 4) + (kw & 3) * 4);
                    b[nt][q] = *(const unsigned int*)((const char*)sW + byte);
                }
            }
#pragma unroll
            for (int mt = 0; mt < 2; mt++)
#pragma unroll
                for (int nt = 0; nt < 8; nt++)
                    mma16816(acc[mt][nt], a[mt], b[nt]);
        }
    }
    __syncthreads();

    // epilogue: bias + relu; layer 0 -> h1 splits/mirror; layer 1 -> head dot
#pragma unroll
    for (int mt = 0; mt < 2; mt++) {
#pragma unroll
        for (int rr = 0; rr < 2; rr++) {
            int lrow = wm + mt * 16 + grp + rr * 8;
            int gr = row0 + lrow;
            float part = 0.f;
#pragma unroll
            for (int nt = 0; nt < 8; nt++) {
                int col = wn + nt * 8 + tg * 2;
                float v0 = acc[mt][nt][rr * 2 + 0] + sbias[col];
                float v1 = acc[mt][nt][rr * 2 + 1] + sbias[col + 1];
                v0 = v0 > 0.f ? v0 : 0.f;
                v1 = v1 > 0.f ? v1 : 0.f;
                if (layer) {
                    part += v0 * swout[col] + v1 * swout[col + 1];
                } else if (gr < n) {
                    __nv_bfloat16 h0 = __float2bfloat16(v0);
                    __nv_bfloat16 h1v = __float2bfloat16(v1);
                    unsigned int hi = ((unsigned)__bfloat16_as_ushort(h1v) << 16) |
                                      __bfloat16_as_ushort(h0);
                    unsigned int lo = pkbf(v0 - __bfloat162float(h0),
                                           v1 - __bfloat162float(h1v));
                    *(unsigned int*)&g_h1b[(long)gr * 128 + col] = hi;
                    *(unsigned int*)&g_h1s[(long)gr * 128 + col] = lo;
                    __half2 hh = __floats2half2_rn(v0, v1);
                    *(unsigned int*)&g_h1h[(long)gr * 128 + col] =
                        *(unsigned int*)&hh;
                }
            }
            if (layer) {
                part += __shfl_xor_sync(0xffffffffu, part, 1);
                part += __shfl_xor_sync(0xffffffffu, part, 2);
                if (tg == 0 && gr < n) atomicAdd(&sdot[lrow], part);
            }
        }
    }
    if (layer) {
        __syncthreads();
        if (tid < 128) {
            int gr = row0 + tid;
            if (gr < n) out[gr] = sdot[tid] + bout[0];
        }
    }
}

// ---------------- launch ---------------------------------------------------
extern "C" void kernel_launch(void* const* d_in, const int* in_sizes, int n_in,
                              void* d_out, int out_size) {
    const float* x    = (const float*)d_in[0];
    const void*  ei   = d_in[1];
    const float* W1l  = (const float*)d_in[2];
    const float* b1l  = (const float*)d_in[3];
    const float* W1r  = (const float*)d_in[4];
    const float* W2l  = (const float*)d_in[5];
    const float* b2l  = (const float*)d_in[6];
    const float* W2r  = (const float*)d_in[7];
    const float* Wout = (const float*)d_in[8];
    const float* bout = (const float*)d_in[9];
    float*       out  = (float*)d_out;

    const int n = in_sizes[0] / D;    // 50000
    const int E = in_sizes[1] / 2;    // 800000
    const int nb = (n + 1023) / 1024;

    // --- prep + CSR build ---
    prep_kernel<<<(n * 32 + 255) / 256, 256>>>((const int*)ei, (const float4*)x,
                                               W1l, W1r, W2l, W2r, n);
    hist_kernel<<<(E + 255) / 256, 256>>>(ei, E);
    scan_lookback_kernel<<<nb, 256>>>(n, nb);
    scatter_kernel<<<(E + 255) / 256, 256>>>(ei, E);

    const int aggBlocks  = (n * 32 + 255) / 256;
    const int gemmBlocks = (n + 127) / 128;

    // --- layer 1 ---
    aggregate_kernel<<<aggBlocks, 256>>>(n, 0);
    mma_gemm_kernel<<<gemmBlocks, 256>>>(b1l, n, 0, Wout, bout, out);

    // --- layer 2 (head fused) ---
    aggregate_kernel<<<aggBlocks, 256>>>(n, 1);
    mma_gemm_kernel<<<gemmBlocks, 256>>>(b2l, n, 1, Wout, bout, out);
}

// round 16
// speedup vs baseline: 1.7284x; 1.6473x over previous
#include <cuda_runtime.h>
#include <cuda_fp16.h>

#define N_NODES 50000
#define N_EDGES 800000
#define D 128

// ---------------- device scratch (no runtime allocation allowed) ----------
__device__ int   g_deg[N_NODES];
__device__ int   g_rowptr[N_NODES + 1];
__device__ int   g_fill[N_NODES];
__device__ int   g_col[N_EDGES];
__device__ int   g_not64;
__device__ int   g_blk_agg[64];
__device__ int   g_blk_incl[64];
__device__ int   g_blk_flag[64];

__device__ __half g_aggh[N_NODES * D];   // fp16 aggregated neighbors
__device__ __half g_xh[N_NODES * D];     // fp16 mirror of x
__device__ __half g_h1h[N_NODES * D];    // fp16 h1 (gather + gemm input)
__device__ __half g_Wh[4 * 128 * 128];   // fp16 Wt: [mat][n][k]

// ---------------- helpers ---------------------------------------------------
__device__ __forceinline__ void cp_async16(unsigned int dst, const void* src) {
    asm volatile("cp.async.ca.shared.global [%0], [%1], 16;"
                 :: "r"(dst), "l"(src) : "memory");
}
__device__ __forceinline__ void cp_async16z(unsigned int dst, const void* src, int sz) {
    asm volatile("cp.async.ca.shared.global [%0], [%1], 16, %2;"
                 :: "r"(dst), "l"(src), "r"(sz) : "memory");
}
__device__ __forceinline__ void cp_commit() {
    asm volatile("cp.async.commit_group;" ::: "memory");
}
__device__ __forceinline__ void cp_wait0() {
    asm volatile("cp.async.wait_group 0;" ::: "memory");
}

// fp16 m16n8k16 row.col mma, fp32 accumulate
__device__ __forceinline__ void mma16816(float* d, const unsigned int* a,
                                         const unsigned int* b) {
    asm volatile(
        "mma.sync.aligned.m16n8k16.row.col.f32.f16.f16.f32 "
        "{%0,%1,%2,%3}, {%4,%5,%6,%7}, {%8,%9}, {%0,%1,%2,%3};"
        : "+f"(d[0]), "+f"(d[1]), "+f"(d[2]), "+f"(d[3])
        : "r"(a[0]), "r"(a[1]), "r"(a[2]), "r"(a[3]), "r"(b[0]), "r"(b[1]));
}

// ---------------- prep: zero + dtype probe + fp16 conversions --------------
__global__ void prep_kernel(const int* __restrict__ ei32,
                            const float4* __restrict__ x,
                            const float* __restrict__ W1l,
                            const float* __restrict__ W1r,
                            const float* __restrict__ W2l,
                            const float* __restrict__ W2r,
                            int n) {
    int i = blockIdx.x * blockDim.x + threadIdx.x;
    if (i < n) g_deg[i] = 0;
    if (i < 64) g_blk_flag[i] = 0;
    if (blockIdx.x == 0) {
        if (threadIdx.x == 0) g_not64 = 0;
        __syncthreads();
        if (threadIdx.x < 256 && ei32[2 * threadIdx.x + 1] != 0)
            atomicOr(&g_not64, 1);
    }
    if (i < 4 * 16384) {
        int m = i >> 14;
        int t = i & 16383;
        int nn = t >> 7, kk = t & 127;
        const float* W = (m == 0) ? W1l : (m == 1) ? W1r : (m == 2) ? W2l : W2r;
        g_Wh[m * 16384 + nn * 128 + kk] = __float2half(W[kk * 128 + nn]);
    }
    if (i < n * 32) {
        float4 v = x[i];
        __half2 h01 = __floats2half2_rn(v.x, v.y);
        __half2 h23 = __floats2half2_rn(v.z, v.w);
        ((uint2*)g_xh)[i] = make_uint2(*(unsigned int*)&h01, *(unsigned int*)&h23);
    }
}

__global__ void hist_kernel(const void* __restrict__ eiv, int E) {
    int e = blockIdx.x * blockDim.x + threadIdx.x;
    if (e >= E) return;
    int d;
    if (g_not64) d = ((const int*)eiv)[E + e];
    else         d = (int)((const long long*)eiv)[E + e];
    atomicAdd(&g_deg[d], 1);
}

__global__ void scan_lookback_kernel(int n, int nb) {
    const int b = blockIdx.x;
    const int t = threadIdx.x;
    const int lane = t & 31, wid = t >> 5;
    int i0 = b * 1024 + t * 4;

    int vals[4]; int local = 0;
#pragma unroll
    for (int u = 0; u < 4; u++) {
        int i = i0 + u;
        vals[u] = (i < n) ? g_deg[i] : 0;
        local += vals[u];
    }
    int incl = local;
#pragma unroll
    for (int off = 1; off < 32; off <<= 1) {
        int u = __shfl_up_sync(0xffffffffu, incl, off);
        if (lane >= off) incl += u;
    }
    __shared__ int ws[8], wexcl[8];
    __shared__ int s_prefix;
    if (lane == 31) ws[wid] = incl;
    __syncthreads();
    if (t < 8) {
        int s = ws[t];
        int si = s;
#pragma unroll
        for (int off = 1; off < 8; off <<= 1) {
            int u = __shfl_up_sync(0xffu, si, off);
            if (t >= off) si += u;
        }
        wexcl[t] = si - s;
    }
    __syncthreads();
    const int total = wexcl[7] + ws[7];

    if (t == 0) {
        g_blk_agg[b] = total;
        __threadfence();
        ((volatile int*)g_blk_flag)[b] = 1;
    }
    if (wid == 0) {
        int prefix = 0;
        int j = b - 1;
        while (j >= 0) {
            int jj = j - lane;
            int f = 0, v = 0;
            if (jj >= 0) {
                do { f = ((volatile int*)g_blk_flag)[jj]; } while (f == 0);
                __threadfence();
                v = (f == 2) ? ((volatile int*)g_blk_incl)[jj]
                             : ((volatile int*)g_blk_agg)[jj];
            }
            unsigned done = __ballot_sync(0xffffffffu, jj >= 0 && f == 2);
            if (done) {
                int fl = __ffs(done) - 1;
                int contrib = (lane <= fl) ? v : 0;
#pragma unroll
                for (int off = 16; off; off >>= 1)
                    contrib += __shfl_xor_sync(0xffffffffu, contrib, off);
                prefix += contrib;
                break;
            } else {
                int contrib = (jj >= 0) ? v : 0;
#pragma unroll
                for (int off = 16; off; off >>= 1)
                    contrib += __shfl_xor_sync(0xffffffffu, contrib, off);
                prefix += contrib;
                j -= 32;
            }
        }
        if (lane == 0) {
            g_blk_incl[b] = prefix + total;
            __threadfence();
            ((volatile int*)g_blk_flag)[b] = 2;
            s_prefix = prefix;
            if (b == nb - 1) g_rowptr[n] = prefix + total;
        }
    }
    __syncthreads();

    int excl = s_prefix + wexcl[wid] + (incl - local);
#pragma unroll
    for (int u = 0; u < 4; u++) {
        int i = i0 + u;
        if (i < n) { g_rowptr[i] = excl; g_fill[i] = excl; }
        excl += vals[u];
    }
}

__global__ void scatter_kernel(const void* __restrict__ eiv, int E) {
    int e = blockIdx.x * blockDim.x + threadIdx.x;
    if (e >= E) return;
    int s, d;
    if (g_not64) {
        s = ((const int*)eiv)[e];
        d = ((const int*)eiv)[E + e];
    } else {
        s = (int)((const long long*)eiv)[e];
        d = (int)((const long long*)eiv)[E + e];
    }
    int pos = atomicAdd(&g_fill[d], 1);
    g_col[pos] = s;
}

// ---------------- mean aggregation: warp/node, fp16 gather -> fp16 out -----
__global__ void aggregate_kernel(int n, int use_h1) {
    int warp = (blockIdx.x * blockDim.x + threadIdx.x) >> 5;
    int lane = threadIdx.x & 31;
    if (warp >= n) return;
    const uint2* __restrict__ src =
        use_h1 ? (const uint2*)g_h1h : (const uint2*)g_xh;
    int beg = g_rowptr[warp];
    int end = g_rowptr[warp + 1];
    float4 acc = make_float4(0.f, 0.f, 0.f, 0.f);
    int e = beg;
    for (; e + 8 <= end; e += 8) {
        int s0 = g_col[e],     s1 = g_col[e + 1], s2 = g_col[e + 2], s3 = g_col[e + 3];
        int s4 = g_col[e + 4], s5 = g_col[e + 5], s6 = g_col[e + 6], s7 = g_col[e + 7];
        uint2 v0 = src[(long)s0 * 32 + lane];
        uint2 v1 = src[(long)s1 * 32 + lane];
        uint2 v2 = src[(long)s2 * 32 + lane];
        uint2 v3 = src[(long)s3 * 32 + lane];
        uint2 v4 = src[(long)s4 * 32 + lane];
        uint2 v5 = src[(long)s5 * 32 + lane];
        uint2 v6 = src[(long)s6 * 32 + lane];
        uint2 v7 = src[(long)s7 * 32 + lane];
#pragma unroll
        for (int q = 0; q < 8; q++) {
            uint2 v = (q == 0) ? v0 : (q == 1) ? v1 : (q == 2) ? v2 : (q == 3) ? v3
                    : (q == 4) ? v4 : (q == 5) ? v5 : (q == 6) ? v6 : v7;
            float2 f0 = __half22float2(*(__half2*)&v.x);
            float2 f1 = __half22float2(*(__half2*)&v.y);
            acc.x += f0.x; acc.y += f0.y; acc.z += f1.x; acc.w += f1.y;
        }
    }
    for (; e + 4 <= end; e += 4) {
        int s0 = g_col[e], s1 = g_col[e + 1], s2 = g_col[e + 2], s3 = g_col[e + 3];
        uint2 v0 = src[(long)s0 * 32 + lane];
        uint2 v1 = src[(long)s1 * 32 + lane];
        uint2 v2 = src[(long)s2 * 32 + lane];
        uint2 v3 = src[(long)s3 * 32 + lane];
#pragma unroll
        for (int q = 0; q < 4; q++) {
            uint2 v = (q == 0) ? v0 : (q == 1) ? v1 : (q == 2) ? v2 : v3;
            float2 f0 = __half22float2(*(__half2*)&v.x);
            float2 f1 = __half22float2(*(__half2*)&v.y);
            acc.x += f0.x; acc.y += f0.y; acc.z += f1.x; acc.w += f1.y;
        }
    }
    for (; e < end; ++e) {
        int s = g_col[e];
        uint2 v = src[(long)s * 32 + lane];
        float2 f0 = __half22float2(*(__half2*)&v.x);
        float2 f1 = __half22float2(*(__half2*)&v.y);
        acc.x += f0.x; acc.y += f0.y; acc.z += f1.x; acc.w += f1.y;
    }
    int deg = end - beg;
    float sc = 1.0f / (float)(deg > 0 ? deg : 1);
    acc.x *= sc; acc.y *= sc; acc.z *= sc; acc.w *= sc;

    __half2 p01 = __floats2half2_rn(acc.x, acc.y);
    __half2 p23 = __floats2half2_rn(acc.z, acc.w);
    ((uint2*)g_aggh)[(long)warp * 32 + lane] =
        make_uint2(*(unsigned int*)&p01, *(unsigned int*)&p23);
}

// ---------------- fp16 mma.sync SAGE GEMM: 2 segments ----------------------
// out = relu(aggh@Wl + bl + Bh@Wr). layer=0: out -> h1h. layer=1: fused head.
__global__ void __launch_bounds__(256, 2)
mma_gemm_kernel(const float* __restrict__ bl, int n, int layer,
                const float* __restrict__ Wout,
                const float* __restrict__ bout,
                float* __restrict__ out) {
    __shared__ __align__(16) __half sA[128 * 64];
    __shared__ __align__(16) __half sW[128 * 64];
    __shared__ float sbias[128];
    __shared__ float swout[128];
    __shared__ float sdot[128];

    const int tid = threadIdx.x;
    const int wid = tid >> 5, lid = tid & 31;
    const int grp = lid >> 2, tg = lid & 3;
    const int wm = (wid & 3) * 32;
    const int wn = (wid >> 2) * 64;
    const int row0 = blockIdx.x * 128;

    const unsigned int sA_addr = (unsigned int)__cvta_generic_to_shared(sA);
    const unsigned int sW_addr = (unsigned int)__cvta_generic_to_shared(sW);

    const __half* Bh  = layer ? g_h1h : g_xh;
    const __half* Wlh = g_Wh + (layer ? 2 : 0) * 16384;
    const __half* Wrh = g_Wh + (layer ? 3 : 1) * 16384;

    if (tid < 128) {
        sbias[tid] = bl[tid];
        sdot[tid] = 0.f;
        if (layer) swout[tid] = Wout[tid];
    }

    const __half* Aseq[2] = { g_aggh, Bh };
    const __half* Wseq[2] = { Wlh, Wrh };

    float acc[2][8][4];
#pragma unroll
    for (int mt = 0; mt < 2; mt++)
#pragma unroll
        for (int nt = 0; nt < 8; nt++)
#pragma unroll
            for (int q = 0; q < 4; q++) acc[mt][nt][q] = 0.f;

    for (int h = 0; h < 4; h++) {
        const int seg = h >> 1;
        const int k0 = (h & 1) * 64;
        const __half* Ap = Aseq[seg];
        const __half* Wp = Wseq[seg];

        __syncthreads();
#pragma unroll
        for (int u = 0; u < 4; u++) {
            int id = tid + u * 256;
            int r = id >> 3, c = id & 7;
            int gr = row0 + r;
            unsigned int dst = sA_addr + r * 128 + ((c ^ (r & 7)) * 16);
            const void* src = Ap + (long)((gr < n) ? gr : 0) * 128 + k0 + c * 8;
            cp_async16z(dst, src, (gr < n) ? 16 : 0);
        }
#pragma unroll
        for (int u = 0; u < 4; u++) {
            int id = tid + u * 256;
            int r = id >> 3, c = id & 7;
            unsigned int dst = sW_addr + r * 128 + ((c ^ (r & 7)) * 16);
            cp_async16(dst, Wp + r * 128 + k0 + c * 8);
        }
        cp_commit();
        cp_wait0();
        __syncthreads();

#pragma unroll
        for (int ks = 0; ks < 4; ks++) {
            const int kw0 = ks * 8;
            unsigned int a[2][4], b[8][2];
#pragma unroll
            for (int mt = 0; mt < 2; mt++) {
                int rb = wm + mt * 16 + grp;
#pragma unroll
                for (int q = 0; q < 4; q++) {
                    int r = rb + ((q & 1) ? 8 : 0);
                    int kw = kw0 + ((q >> 1) ? 4 : 0) + tg;
                    unsigned int byte = (unsigned)(r * 128 +
                        (((kw >> 2) ^ (r & 7)) << 4) + (kw & 3) * 4);
                    a[mt][q] = *(const unsigned int*)((const char*)sA + byte);
                }
            }
#pragma unroll
            for (int nt = 0; nt < 8; nt++) {
                int nr = wn + nt * 8 + grp;
#pragma unroll
                for (int q = 0; q < 2; q++) {
                    int kw = kw0 + (q ? 4 : 0) + tg;
                    unsigned int byte = (unsigned)(nr * 128 +
                        (((kw >> 2) ^ (nr & 7)) << 4) + (kw & 3) * 4);
                    b[nt][q] = *(const unsigned int*)((const char*)sW + byte);
                }
            }
#pragma unroll
            for (int mt = 0; mt < 2; mt++)
#pragma unroll
                for (int nt = 0; nt < 8; nt++)
                    mma16816(acc[mt][nt], a[mt], b[nt]);
        }
    }
    __syncthreads();

    // epilogue: bias + relu; layer 0 -> h1h; layer 1 -> fused head dot
#pragma unroll
    for (int mt = 0; mt < 2; mt++) {
#pragma unroll
        for (int rr = 0; rr < 2; rr++) {
            int lrow = wm + mt * 16 + grp + rr * 8;
            int gr = row0 + lrow;
            float part = 0.f;
#pragma unroll
            for (int nt = 0; nt < 8; nt++) {
                int col = wn + nt * 8 + tg * 2;
                float v0 = acc[mt][nt][rr * 2 + 0] + sbias[col];
                float v1 = acc[mt][nt][rr * 2 + 1] + sbias[col + 1];
                v0 = v0 > 0.f ? v0 : 0.f;
                v1 = v1 > 0.f ? v1 : 0.f;
                if (layer) {
                    part += v0 * swout[col] + v1 * swout[col + 1];
                } else if (gr < n) {
                    __half2 hh = __floats2half2_rn(v0, v1);
                    *(unsigned int*)&g_h1h[(long)gr * 128 + col] =
                        *(unsigned int*)&hh;
                }
            }
            if (layer) {
                part += __shfl_xor_sync(0xffffffffu, part, 1);
                part += __shfl_xor_sync(0xffffffffu, part, 2);
                if (tg == 0 && gr < n) atomicAdd(&sdot[lrow], part);
            }
        }
    }
    if (layer) {
        __syncthreads();
        if (tid < 128) {
            int gr = row0 + tid;
            if (gr < n) out[gr] = sdot[tid] + bout[0];
        }
    }
}

// ---------------- launch ---------------------------------------------------
extern "C" void kernel_launch(void* const* d_in, const int* in_sizes, int n_in,
                              void* d_out, int out_size) {
    const float* x    = (const float*)d_in[0];
    const void*  ei   = d_in[1];
    const float* W1l  = (const float*)d_in[2];
    const float* b1l  = (const float*)d_in[3];
    const float* W1r  = (const float*)d_in[4];
    const float* W2l  = (const float*)d_in[5];
    const float* b2l  = (const float*)d_in[6];
    const float* W2r  = (const float*)d_in[7];
    const float* Wout = (const float*)d_in[8];
    const float* bout = (const float*)d_in[9];
    float*       out  = (float*)d_out;

    const int n = in_sizes[0] / D;    // 50000
    const int E = in_sizes[1] / 2;    // 800000
    const int nb = (n + 1023) / 1024;

    // --- prep + CSR build ---
    prep_kernel<<<(n * 32 + 255) / 256, 256>>>((const int*)ei, (const float4*)x,
                                               W1l, W1r, W2l, W2r, n);
    hist_kernel<<<(E + 255) / 256, 256>>>(ei, E);
    scan_lookback_kernel<<<nb, 256>>>(n, nb);
    scatter_kernel<<<(E + 255) / 256, 256>>>(ei, E);

    const int aggBlocks  = (n * 32 + 255) / 256;
    const int gemmBlocks = (n + 127) / 128;

    // --- layer 1 ---
    aggregate_kernel<<<aggBlocks, 256>>>(n, 0);
    mma_gemm_kernel<<<gemmBlocks, 256>>>(b1l, n, 0, Wout, bout, out);

    // --- layer 2 (head fused) ---
    aggregate_kernel<<<aggBlocks, 256>>>(n, 1);
    mma_gemm_kernel<<<gemmBlocks, 256>>>(b2l, n, 1, Wout, bout, out);
}